// round 3
// baseline (speedup 1.0000x reference)
#include <cuda_runtime.h>

#define K 32
#define NELEM (32*64*1024)
#define THREADS 256
#define GRID 512

// Scratch accumulators (no allocations allowed).
__device__ float g_sumP[K];
__device__ float g_quant;

__global__ void ssq_init_kernel() {
    int t = threadIdx.x;
    if (t < K) g_sumP[t] = 0.0f;
    if (t == K) g_quant = 0.0f;
}

__device__ __forceinline__ float ex2f_(float x) {
    float r; asm("ex2.approx.ftz.f32 %0, %1;" : "=f"(r) : "f"(x)); return r;
}
__device__ __forceinline__ float rcpf_(float x) {
    float r; asm("rcp.approx.ftz.f32 %0, %1;" : "=f"(r) : "f"(x)); return r;
}
__device__ __forceinline__ float rsqf_(float x) {
    float r; asm("rsqrt.approx.ftz.f32 %0, %1;" : "=f"(r) : "f"(x)); return r;
}

// exp(ALPHA*d) = exp(-10 d) = (exp(-5 d))^2 = (ex2(C2*d))^2, C2 = -5*log2(e)
__global__ __launch_bounds__(THREADS, 2)
void ssq_main_kernel(const float* __restrict__ x,
                     const float* __restrict__ bins,
                     float* __restrict__ out)
{
    // Bins in registers (loop-invariant).
    float rb[K];
    #pragma unroll
    for (int k = 0; k < K; k++) rb[k] = __ldg(&bins[k]);
    float sumB = 0.0f;
    #pragma unroll
    for (int k = 0; k < K; k++) sumB += rb[k];
    const float epsB = 1e-10f * sumB;   // EPS * sum(bins) term of bit_code

    float sumP[K];
    #pragma unroll
    for (int k = 0; k < K; k++) sumP[k] = 0.0f;
    float qacc = 0.0f;

    const float C2 = -7.21347520444482f;  // ALPHA * log2(e) / 2

    const int tid = blockIdx.x * THREADS + threadIdx.x;
    const int nth = gridDim.x * THREADS;
    const float4* x4 = (const float4*)x;
    float4* o4 = (float4*)out;
    const int n4 = NELEM / 4;

    for (int i = tid; i < n4; i += nth) {
        float4 xv = x4[i];
        float xs[4] = {xv.x, xv.y, xv.z, xv.w};
        float os[4];
        #pragma unroll
        for (int c = 0; c < 4; c++) {
            const float xe = xs[c];
            float e[K];
            float S = 0.0f, Hs = 0.0f, bitRaw = 0.0f;
            #pragma unroll
            for (int k = 0; k < K; k++) {
                float d  = fabsf(xe - rb[k]);
                float h  = ex2f_(C2 * d);     // exp(-5 d)   (1 MUFU per bin)
                float ee = h * h;             // exp(-10 d)
                S  += ee;
                Hs += h;                      // for sum_k sqrt(soft_k)
                bitRaw = fmaf(ee, rb[k], bitRaw);
                e[k] = ee;
            }
            float invS = rcpf_(S);
            float rs   = rsqf_(S);
            qacc = fmaf(Hs, rs, qacc);        // sum_k sqrt(e_k/S) = Hs / sqrt(S)
            #pragma unroll
            for (int k = 0; k < K; k++)
                sumP[k] = fmaf(e[k], invS, sumP[k]);   // accumulate soft_k
            os[c] = fmaf(bitRaw, invS, epsB);          // bit_code element
        }
        float4 ov; ov.x = os[0]; ov.y = os[1]; ov.z = os[2]; ov.w = os[3];
        o4[i] = ov;
    }

    // Warp xor-reduce (all lanes end with warp totals; static indices only).
    #pragma unroll
    for (int s = 16; s > 0; s >>= 1) {
        qacc += __shfl_xor_sync(0xffffffffu, qacc, s);
        #pragma unroll
        for (int k = 0; k < K; k++)
            sumP[k] += __shfl_xor_sync(0xffffffffu, sumP[k], s);
    }

    __shared__ float sP[THREADS / 32][K];
    __shared__ float sQ[THREADS / 32];
    const int w = threadIdx.x >> 5, lane = threadIdx.x & 31;
    if (lane == 0) {
        sQ[w] = qacc;
        #pragma unroll
        for (int k = 0; k < K; k++) sP[w][k] = sumP[k];
    }
    __syncthreads();
    if (threadIdx.x < K) {
        float t = 0.0f;
        #pragma unroll
        for (int ww = 0; ww < THREADS / 32; ww++) t += sP[ww][threadIdx.x];
        atomicAdd(&g_sumP[threadIdx.x], t);
    }
    if (threadIdx.x == 0) {
        float q = 0.0f;
        #pragma unroll
        for (int ww = 0; ww < THREADS / 32; ww++) q += sQ[ww];
        atomicAdd(&g_quant, q);
    }
}

__global__ void ssq_final_kernel(float* __restrict__ out) {
    const float invN = 1.0f / (float)NELEM;
    int k = threadIdx.x;  // 32 threads
    float p = fmaf(g_sumP[k], invN, 1e-10f);  // mean(soft_k) + EPS
    float t = -p * logf(p);
    #pragma unroll
    for (int s = 16; s > 0; s >>= 1)
        t += __shfl_xor_sync(0xffffffffu, t, s);
    if (k == 0) {
        out[NELEM]     = t;                 // code entropy
        out[NELEM + 1] = 0.0f;              // TAU
        out[NELEM + 2] = g_quant * invN;    // quant loss
        out[NELEM + 3] = 0.0f;              // TAU2
    }
}

extern "C" void kernel_launch(void* const* d_in, const int* in_sizes, int n_in,
                              void* d_out, int out_size)
{
    const float* x    = (const float*)d_in[0];
    const float* bins = (const float*)d_in[1];
    // Defensive: pick by size (bins has K elements).
    if (n_in >= 2 && in_sizes[0] == K && in_sizes[1] != K) {
        const float* tmp = x; x = bins; bins = tmp;
    }
    float* out = (float*)d_out;

    ssq_init_kernel<<<1, 64>>>();
    ssq_main_kernel<<<GRID, THREADS>>>(x, bins, out);
    ssq_final_kernel<<<1, 32>>>(out);
}

// round 4
// speedup vs baseline: 1.0696x; 1.0696x over previous
#include <cuda_runtime.h>

#define K 32
#define NELEM (32*64*1024)
#define THREADS 128
#define GRID 296

typedef unsigned long long u64;

// Per-block partials: [value][block]; values 0..31 = sum of soft_k, 32 = quant sum.
// Every block writes its own slot every run -> no init kernel, no atomics.
__device__ float g_part[K + 1][GRID];

__device__ __forceinline__ float ex2f_(float x) {
    float r; asm("ex2.approx.ftz.f32 %0, %1;" : "=f"(r) : "f"(x)); return r;
}
__device__ __forceinline__ float rcpf_(float x) {
    float r; asm("rcp.approx.ftz.f32 %0, %1;" : "=f"(r) : "f"(x)); return r;
}
__device__ __forceinline__ float rsqf_(float x) {
    float r; asm("rsqrt.approx.ftz.f32 %0, %1;" : "=f"(r) : "f"(x)); return r;
}
__device__ __forceinline__ u64 pack2(float lo, float hi) {
    u64 r; asm("mov.b64 %0, {%1, %2};" : "=l"(r) : "f"(lo), "f"(hi)); return r;
}
__device__ __forceinline__ float lo2(u64 v) {
    float lo, hi; asm("mov.b64 {%0, %1}, %2;" : "=f"(lo), "=f"(hi) : "l"(v)); return lo;
}
__device__ __forceinline__ float hi2(u64 v) {
    float lo, hi; asm("mov.b64 {%0, %1}, %2;" : "=f"(lo), "=f"(hi) : "l"(v)); return hi;
}

#define MUL2(o, a, b)    asm("mul.rn.f32x2 %0, %1, %2;"     : "=l"(o) : "l"(a), "l"(b))
#define ADD2(o, a, b)    asm("add.rn.f32x2 %0, %1, %2;"     : "=l"(o) : "l"(a), "l"(b))
#define FMA2(o, a, b, c) asm("fma.rn.f32x2 %0, %1, %2, %3;" : "=l"(o) : "l"(a), "l"(b), "l"(c))

// exp(-10|x-b|) = h^2,  h = exp(-5|x-b|) = min( exp(-5x)exp(5b), exp(5x)exp(-5b) )
__global__ __launch_bounds__(THREADS, 2)
void ssq_main_kernel(const float* __restrict__ x,
                     const float* __restrict__ bins,
                     float* __restrict__ out)
{
    const float CC = 7.21347520444482f;   // 5 * log2(e)

    // Packed per-bin-pair constants: {exp(5b0),exp(5b1)}, {exp(-5b0),exp(-5b1)}, {b0,b1}
    u64 c2p[K/2], d2p[K/2], bp[K/2];
    float sumB = 0.0f;
    #pragma unroll
    for (int j = 0; j < K/2; j++) {
        float b0 = __ldg(&bins[2*j]);
        float b1 = __ldg(&bins[2*j + 1]);
        sumB += b0 + b1;
        c2p[j] = pack2(ex2f_( CC * b0), ex2f_( CC * b1));
        d2p[j] = pack2(ex2f_(-CC * b0), ex2f_(-CC * b1));
        bp[j]  = pack2(b0, b1);
    }
    const float epsB = 1e-10f * sumB;     // EPS * sum(bins) term of bit_code

    u64 sumP2[K/2];
    #pragma unroll
    for (int j = 0; j < K/2; j++) sumP2[j] = 0ull;
    float qacc = 0.0f;

    const int tid = blockIdx.x * THREADS + threadIdx.x;
    const int nth = GRID * THREADS;
    const float4* x4 = (const float4*)x;
    float4* o4 = (float4*)out;
    const int n4 = NELEM / 4;

    for (int i = tid; i < n4; i += nth) {
        float4 xv = x4[i];
        float xs[4] = {xv.x, xv.y, xv.z, xv.w};
        float os[4];
        #pragma unroll
        for (int c = 0; c < 4; c++) {
            const float xe = xs[c];
            const float t  = CC * xe;
            const float A2 = ex2f_(-t);       // exp(-5x)
            const float B2 = ex2f_( t);       // exp(+5x)
            const u64 A2s = pack2(A2, A2);
            const u64 B2s = pack2(B2, B2);

            u64 Sp = 0ull, Hp = 0ull, Bp = 0ull;
            u64 ep[K/2];
            #pragma unroll
            for (int j = 0; j < K/2; j++) {
                u64 u, v;
                MUL2(u, A2s, c2p[j]);                       // exp(5(b-x))
                MUL2(v, B2s, d2p[j]);                       // exp(5(x-b))
                float h0 = fminf(lo2(u), lo2(v));           // FMNMX (alu pipe)
                float h1 = fminf(hi2(u), hi2(v));
                u64 h = pack2(h0, h1);                      // exp(-5|x-b|)
                u64 e;
                MUL2(e, h, h);                              // exp(-10|x-b|)
                ADD2(Sp, Sp, e);
                ADD2(Hp, Hp, h);
                FMA2(Bp, e, bp[j], Bp);
                ep[j] = e;
            }
            const float S      = lo2(Sp) + hi2(Sp);
            const float Hs     = lo2(Hp) + hi2(Hp);
            const float bitRaw = lo2(Bp) + hi2(Bp);
            const float invS   = rcpf_(S);
            qacc = fmaf(Hs, rsqf_(S), qacc);                // sum_k sqrt(soft_k)
            const u64 invSs = pack2(invS, invS);
            #pragma unroll
            for (int j = 0; j < K/2; j++)
                FMA2(sumP2[j], ep[j], invSs, sumP2[j]);     // accumulate soft_k
            os[c] = fmaf(bitRaw, invS, epsB);               // bit_code element
        }
        float4 ov; ov.x = os[0]; ov.y = os[1]; ov.z = os[2]; ov.w = os[3];
        o4[i] = ov;
    }

    // Warp xor-reduce (u64 shuffles = 2x SHFL each; only once per kernel).
    #pragma unroll
    for (int m = 16; m > 0; m >>= 1) {
        qacc += __shfl_xor_sync(0xffffffffu, qacc, m);
        #pragma unroll
        for (int j = 0; j < K/2; j++) {
            u64 o = __shfl_xor_sync(0xffffffffu, sumP2[j], m);
            ADD2(sumP2[j], sumP2[j], o);
        }
    }

    __shared__ float sP[THREADS/32][K + 1];
    const int w = threadIdx.x >> 5, lane = threadIdx.x & 31;
    if (lane == 0) {
        #pragma unroll
        for (int j = 0; j < K/2; j++) {
            sP[w][2*j]     = lo2(sumP2[j]);
            sP[w][2*j + 1] = hi2(sumP2[j]);
        }
        sP[w][K] = qacc;
    }
    __syncthreads();
    if (threadIdx.x <= K) {
        float tsum = 0.0f;
        #pragma unroll
        for (int ww = 0; ww < THREADS/32; ww++) tsum += sP[ww][threadIdx.x];
        g_part[threadIdx.x][blockIdx.x] = tsum;
    }
}

// One block, 288 threads (9 warps): 8 threads per value x 33 values, then entropy.
__global__ void ssq_final_kernel(float* __restrict__ out) {
    __shared__ float vals[K + 1];
    const int t = threadIdx.x;
    const int v = t >> 3, s = t & 7;
    float acc = 0.0f;
    if (v <= K) {
        for (int g = s; g < GRID; g += 8) acc += g_part[v][g];
    }
    acc += __shfl_xor_sync(0xffffffffu, acc, 1);
    acc += __shfl_xor_sync(0xffffffffu, acc, 2);
    acc += __shfl_xor_sync(0xffffffffu, acc, 4);
    if (v <= K && s == 0) vals[v] = acc;
    __syncthreads();
    if (t < K) {
        const float invN = 1.0f / (float)NELEM;
        float p = fmaf(vals[t], invN, 1e-10f);    // mean(soft_k) + EPS
        float e = -p * logf(p);
        #pragma unroll
        for (int m = 16; m > 0; m >>= 1)
            e += __shfl_xor_sync(0xffffffffu, e, m);
        if (t == 0) {
            out[NELEM]     = e;                    // code entropy
            out[NELEM + 1] = 0.0f;                 // TAU
            out[NELEM + 2] = vals[K] * invN;       // quant loss
            out[NELEM + 3] = 0.0f;                 // TAU2
        }
    }
}

extern "C" void kernel_launch(void* const* d_in, const int* in_sizes, int n_in,
                              void* d_out, int out_size)
{
    const float* x    = (const float*)d_in[0];
    const float* bins = (const float*)d_in[1];
    if (n_in >= 2 && in_sizes[0] == K && in_sizes[1] != K) {
        const float* tmp = x; x = bins; bins = tmp;
    }
    float* out = (float*)d_out;

    ssq_main_kernel<<<GRID, THREADS>>>(x, bins, out);
    ssq_final_kernel<<<1, 288>>>(out);
}

// round 5
// speedup vs baseline: 1.1509x; 1.0760x over previous
#include <cuda_runtime.h>

#define K 32
#define NELEM (32*64*1024)
#define THREADS 128
#define GRID 296

typedef unsigned long long u64;

// Tiny global accumulators. Zero-initialized at module load; the last block of
// every execution resets them to zero after use, so graph replays are clean.
__device__ float g_accum[K + 1];
__device__ unsigned int g_count;

__device__ __forceinline__ float ex2f_(float x) {
    float r; asm("ex2.approx.ftz.f32 %0, %1;" : "=f"(r) : "f"(x)); return r;
}
__device__ __forceinline__ float rcpf_(float x) {
    float r; asm("rcp.approx.ftz.f32 %0, %1;" : "=f"(r) : "f"(x)); return r;
}
__device__ __forceinline__ float rsqf_(float x) {
    float r; asm("rsqrt.approx.ftz.f32 %0, %1;" : "=f"(r) : "f"(x)); return r;
}
__device__ __forceinline__ u64 pack2(float lo, float hi) {
    u64 r; asm("mov.b64 %0, {%1, %2};" : "=l"(r) : "f"(lo), "f"(hi)); return r;
}
__device__ __forceinline__ float lo2(u64 v) {
    float lo, hi; asm("mov.b64 {%0, %1}, %2;" : "=f"(lo), "=f"(hi) : "l"(v)); return lo;
}
__device__ __forceinline__ float hi2(u64 v) {
    float lo, hi; asm("mov.b64 {%0, %1}, %2;" : "=f"(lo), "=f"(hi) : "l"(v)); return hi;
}

#define MUL2(o, a, b)    asm("mul.rn.f32x2 %0, %1, %2;"     : "=l"(o) : "l"(a), "l"(b))
#define ADD2(o, a, b)    asm("add.rn.f32x2 %0, %1, %2;"     : "=l"(o) : "l"(a), "l"(b))
#define FMA2(o, a, b, c) asm("fma.rn.f32x2 %0, %1, %2, %3;" : "=l"(o) : "l"(a), "l"(b), "l"(c))

// exp(-10|x-b|) = h^2,  h = exp(-5|x-b|) = min( exp(-5x)exp(5b), exp(5x)exp(-5b) )
__global__ __launch_bounds__(THREADS, 2)
void ssq_fused_kernel(const float* __restrict__ x,
                      const float* __restrict__ bins,
                      float* __restrict__ out)
{
    const float CC = 7.21347520444482f;   // 5 * log2(e)

    // Packed per-bin-pair constants: {exp(5b0),exp(5b1)}, {exp(-5b0),exp(-5b1)}, {b0,b1}
    u64 c2p[K/2], d2p[K/2], bp[K/2];
    float sumB = 0.0f;
    #pragma unroll
    for (int j = 0; j < K/2; j++) {
        float b0 = __ldg(&bins[2*j]);
        float b1 = __ldg(&bins[2*j + 1]);
        sumB += b0 + b1;
        c2p[j] = pack2(ex2f_( CC * b0), ex2f_( CC * b1));
        d2p[j] = pack2(ex2f_(-CC * b0), ex2f_(-CC * b1));
        bp[j]  = pack2(b0, b1);
    }
    const float epsB = 1e-10f * sumB;     // EPS * sum(bins) term of bit_code

    u64 sumP2[K/2];
    #pragma unroll
    for (int j = 0; j < K/2; j++) sumP2[j] = 0ull;
    float qacc = 0.0f;

    const int tid = blockIdx.x * THREADS + threadIdx.x;
    const int nth = GRID * THREADS;
    const float4* x4 = (const float4*)x;
    float4* o4 = (float4*)out;
    const int n4 = NELEM / 4;

    for (int i = tid; i < n4; i += nth) {
        float4 xv = x4[i];
        float xs[4] = {xv.x, xv.y, xv.z, xv.w};
        float os[4];
        #pragma unroll
        for (int c = 0; c < 4; c++) {
            const float xe = xs[c];
            const float t  = CC * xe;
            const float A2 = ex2f_(-t);       // exp(-5x)
            const float B2 = ex2f_( t);       // exp(+5x)
            const u64 A2s = pack2(A2, A2);
            const u64 B2s = pack2(B2, B2);

            u64 Sp = 0ull, Hp = 0ull, Bpk = 0ull;
            u64 ep[K/2];
            #pragma unroll
            for (int j = 0; j < K/2; j++) {
                u64 u, v;
                MUL2(u, A2s, c2p[j]);                       // exp(5(b-x))
                MUL2(v, B2s, d2p[j]);                       // exp(5(x-b))
                float h0 = fminf(lo2(u), lo2(v));           // FMNMX (alu pipe)
                float h1 = fminf(hi2(u), hi2(v));
                u64 h = pack2(h0, h1);                      // exp(-5|x-b|)
                u64 e;
                MUL2(e, h, h);                              // exp(-10|x-b|)
                ADD2(Sp, Sp, e);
                ADD2(Hp, Hp, h);
                FMA2(Bpk, e, bp[j], Bpk);
                ep[j] = e;
            }
            const float S      = lo2(Sp) + hi2(Sp);
            const float Hs     = lo2(Hp) + hi2(Hp);
            const float bitRaw = lo2(Bpk) + hi2(Bpk);
            const float invS   = rcpf_(S);
            qacc = fmaf(Hs, rsqf_(S), qacc);                // sum_k sqrt(soft_k)
            const u64 invSs = pack2(invS, invS);
            #pragma unroll
            for (int j = 0; j < K/2; j++)
                FMA2(sumP2[j], ep[j], invSs, sumP2[j]);     // accumulate soft_k
            os[c] = fmaf(bitRaw, invS, epsB);               // bit_code element
        }
        float4 ov; ov.x = os[0]; ov.y = os[1]; ov.z = os[2]; ov.w = os[3];
        o4[i] = ov;
    }

    // ---- Per-block reduction ----
    #pragma unroll
    for (int m = 16; m > 0; m >>= 1) {
        qacc += __shfl_xor_sync(0xffffffffu, qacc, m);
        #pragma unroll
        for (int j = 0; j < K/2; j++) {
            u64 o = __shfl_xor_sync(0xffffffffu, sumP2[j], m);
            ADD2(sumP2[j], sumP2[j], o);
        }
    }

    __shared__ float sP[THREADS/32][K + 1];
    __shared__ int sLast;
    const int w = threadIdx.x >> 5, lane = threadIdx.x & 31;
    if (lane == 0) {
        #pragma unroll
        for (int j = 0; j < K/2; j++) {
            sP[w][2*j]     = lo2(sumP2[j]);
            sP[w][2*j + 1] = hi2(sumP2[j]);
        }
        sP[w][K] = qacc;
    }
    __syncthreads();
    if (threadIdx.x <= K) {
        float tsum = 0.0f;
        #pragma unroll
        for (int ww = 0; ww < THREADS/32; ww++) tsum += sP[ww][threadIdx.x];
        atomicAdd(&g_accum[threadIdx.x], tsum);
    }
    __syncthreads();

    // ---- Last-block finalization (self-cleaning for graph replay) ----
    if (threadIdx.x == 0) {
        __threadfence();
        unsigned int arrived = atomicAdd(&g_count, 1u);
        sLast = (arrived == GRID - 1u) ? 1 : 0;
    }
    __syncthreads();
    if (sLast) {
        __threadfence();
        if (threadIdx.x < 32) {
            const float invN = 1.0f / (float)NELEM;
            volatile float* ga = g_accum;
            float p = fmaf(ga[threadIdx.x], invN, 1e-10f);  // mean(soft_k) + EPS
            float e = -p * logf(p);
            #pragma unroll
            for (int m = 16; m > 0; m >>= 1)
                e += __shfl_xor_sync(0xffffffffu, e, m);
            if (threadIdx.x == 0) {
                out[NELEM]     = e;                  // code entropy
                out[NELEM + 1] = 0.0f;               // TAU
                out[NELEM + 2] = ga[K] * invN;       // quant loss
                out[NELEM + 3] = 0.0f;               // TAU2
            }
        }
        __syncthreads();
        // Reset globals for the next graph replay (after all reads).
        if (threadIdx.x <= K) g_accum[threadIdx.x] = 0.0f;
        if (threadIdx.x == 0) g_count = 0u;
    }
}

extern "C" void kernel_launch(void* const* d_in, const int* in_sizes, int n_in,
                              void* d_out, int out_size)
{
    const float* x    = (const float*)d_in[0];
    const float* bins = (const float*)d_in[1];
    if (n_in >= 2 && in_sizes[0] == K && in_sizes[1] != K) {
        const float* tmp = x; x = bins; bins = tmp;
    }
    float* out = (float*)d_out;

    ssq_fused_kernel<<<GRID, THREADS>>>(x, bins, out);
}